// round 16
// baseline (speedup 1.0000x reference)
#include <cuda_runtime.h>
#include <cuda_fp16.h>
#include <cstdint>

#define N_NODES 100000
#define D 128
#define N_EDGES 400000
#define BN_EPS 1e-5f

#define GEMM_WARPS 8
#define TM 8            // rows per warp
#define WP2 66          // packed-W row stride in ull (64 pairs + 2 pad)

#define ELLW 32         // padded edges per node; P(deg>32)*N ~ 1e-15 for Poisson(4)

#define CS_BLOCKS 592
#define PRE_T 256
#define BUILD_BLOCKS ((N_EDGES + PRE_T - 1) / PRE_T)
#define PRE_BLOCKS (CS_BLOCKS + BUILD_BLOCKS)

// ---------------------------------------------------------------------------
// Scratch (device globals only). Zero-initialized; k_agg restores zero state.
// ---------------------------------------------------------------------------
__device__ float  g_sum[D];
__device__ float  g_sumsq[D];
__device__ float  g_h[(size_t)N_NODES * D];     // fp32 h (own-row h^2 path)
__device__ __half g_h16[(size_t)N_NODES * D];   // fp16 h (edge-gather path)

__device__ int   g_cnt[N_NODES];
__device__ int2  g_ell[(size_t)N_NODES * ELLW];

// ---------------------------------------------------------------------------
// K1 "pre": fused column-stats + ELL build (two block ranges). [frozen]
// ---------------------------------------------------------------------------
__global__ void __launch_bounds__(PRE_T) k_pre(const float4* __restrict__ x4,
                                               const int* __restrict__ eidx,
                                               const float* __restrict__ ew) {
    if (blockIdx.x < CS_BLOCKS) {
        const int N4 = N_NODES * D / 4;
        int gtid = blockIdx.x * PRE_T + threadIdx.x;

        float s0 = 0.f, s1 = 0.f, s2 = 0.f, s3 = 0.f;
        float q0 = 0.f, q1 = 0.f, q2 = 0.f, q3 = 0.f;
#pragma unroll 8
        for (int i = gtid; i < N4; i += CS_BLOCKS * PRE_T) {
            float4 v = __ldg(&x4[i]);
            s0 += v.x; q0 += v.x * v.x;
            s1 += v.y; q1 += v.y * v.y;
            s2 += v.z; q2 += v.z * v.z;
            s3 += v.w; q3 += v.w * v.w;
        }

        __shared__ float ss[D];
        __shared__ float sq[D];
        int t = threadIdx.x;
        if (t < D) { ss[t] = 0.f; sq[t] = 0.f; }
        __syncthreads();

        int c0 = (gtid & 31) * 4;
        atomicAdd(&ss[c0 + 0], s0); atomicAdd(&sq[c0 + 0], q0);
        atomicAdd(&ss[c0 + 1], s1); atomicAdd(&sq[c0 + 1], q1);
        atomicAdd(&ss[c0 + 2], s2); atomicAdd(&sq[c0 + 2], q2);
        atomicAdd(&ss[c0 + 3], s3); atomicAdd(&sq[c0 + 3], q3);
        __syncthreads();

        if (t < D) {
            atomicAdd(&g_sum[t], ss[t]);
            atomicAdd(&g_sumsq[t], sq[t]);
        }
    } else {
        int e = (blockIdx.x - CS_BLOCKS) * PRE_T + threadIdx.x;
        if (e >= N_EDGES) return;
        int r = eidx[e];
        int c = eidx[N_EDGES + e];
        float w = ew[e];
        int pos = atomicAdd(&g_cnt[r], 1);
        if (pos < ELLW) {
            g_ell[(size_t)r * ELLW + pos] = make_int2(c, __float_as_int(w));
        }
    }
}

// ---------------------------------------------------------------------------
// K2: fused stats -> BN -> ReLU -> GEMM (R11 configuration, frozen).
// Writes g_h (fp32) + g_h16 (fp16 gather shadow).
// ---------------------------------------------------------------------------
extern __shared__ float sm_gemm[];

__global__ void __launch_bounds__(256, 2) k_gemm(const float* __restrict__ x,
                                                 const float* __restrict__ W,
                                                 const float* __restrict__ gamma,
                                                 const float* __restrict__ beta) {
    unsigned long long* Wp = (unsigned long long*)sm_gemm;    // D * WP2 ull
    float* ysh = (float*)(Wp + D * WP2);                      // GEMM_WARPS*TM*D
    float* ssc = ysh + GEMM_WARPS * TM * D;                   // D
    float* ssh = ssc + D;                                     // D

    int tid = threadIdx.x;

    for (int i = tid; i < D * (D / 2); i += blockDim.x) {
        int jp = i / D;
        int k = i - jp * D;
        float w0 = W[(2 * jp) * D + k];
        float w1 = W[(2 * jp + 1) * D + k];
        unsigned long long pk;
        asm("mov.b64 %0, {%1,%2};" : "=l"(pk) : "f"(w0), "f"(w1));
        Wp[k * WP2 + jp] = pk;
    }
    if (tid < D) {
        const float inv_n = 1.f / (float)N_NODES;
        float mu = g_sum[tid] * inv_n;
        float var = g_sumsq[tid] * inv_n - mu * mu;
        float rs = rsqrtf(var + BN_EPS);
        float sc = gamma[tid] * rs;
        ssc[tid] = sc;
        ssh[tid] = beta[tid] - mu * sc;
    }
    __syncthreads();

    int warp = tid >> 5;
    int lane = tid & 31;
    float* myY = ysh + warp * TM * D;

    float sc[4], sh[4];
#pragma unroll
    for (int i = 0; i < 4; i++) {
        sc[i] = ssc[4 * lane + i];
        sh[i] = ssh[4 * lane + i];
    }

    const int ntiles = (N_NODES + GEMM_WARPS * TM - 1) / (GEMM_WARPS * TM);
    for (int tile = blockIdx.x; tile < ntiles; tile += gridDim.x) {
        int row0 = tile * (GEMM_WARPS * TM) + warp * TM;

        __syncwarp();
#pragma unroll
        for (int r = 0; r < TM; r++) {
            int row = row0 + r;
            if (row < N_NODES) {
                float4 v = *(const float4*)&x[(size_t)row * D + 4 * lane];
                v.x = fmaxf(0.f, fmaf(v.x, sc[0], sh[0]));
                v.y = fmaxf(0.f, fmaf(v.y, sc[1], sh[1]));
                v.z = fmaxf(0.f, fmaf(v.z, sc[2], sh[2]));
                v.w = fmaxf(0.f, fmaf(v.w, sc[3], sh[3]));
                *(float4*)&myY[r * D + 4 * lane] = v;
            }
        }
        __syncwarp();

        unsigned long long acc[TM][2];
#pragma unroll
        for (int r = 0; r < TM; r++) { acc[r][0] = 0ULL; acc[r][1] = 0ULL; }

#pragma unroll 8
        for (int k = 0; k < D; k++) {
            unsigned long long w01, w23;
            {
                ulonglong2 wp = *(const ulonglong2*)&Wp[k * WP2 + 2 * lane];
                w01 = wp.x;
                w23 = wp.y;
            }
#pragma unroll
            for (int r = 0; r < TM; r++) {
                float yv = myY[r * D + k];
                unsigned long long yy;
                asm("mov.b64 %0, {%1,%1};" : "=l"(yy) : "f"(yv));
                asm("fma.rn.f32x2 %0, %1, %2, %0;" : "+l"(acc[r][0]) : "l"(yy), "l"(w01));
                asm("fma.rn.f32x2 %0, %1, %2, %0;" : "+l"(acc[r][1]) : "l"(yy), "l"(w23));
            }
        }

#pragma unroll
        for (int r = 0; r < TM; r++) {
            int row = row0 + r;
            if (row < N_NODES) {
                float4 hv;
                asm("mov.b64 {%0,%1}, %2;" : "=f"(hv.x), "=f"(hv.y) : "l"(acc[r][0]));
                asm("mov.b64 {%0,%1}, %2;" : "=f"(hv.z), "=f"(hv.w) : "l"(acc[r][1]));
                *(float4*)&g_h[(size_t)row * D + 4 * lane] = hv;
                __half2 p0 = __floats2half2_rn(hv.x, hv.y);
                __half2 p1 = __floats2half2_rn(hv.z, hv.w);
                uint2 pk;
                pk.x = *(const unsigned int*)&p0;
                pk.y = *(const unsigned int*)&p1;
                *(uint2*)&g_h16[(size_t)row * D + 4 * lane] = pk;
            }
        }
    }
}

// ---------------------------------------------------------------------------
// K3: ELL aggregation, latency-optimized:
//   - cnt, row[lane] (coalesced), AND own-row h issued together up front
//   - entries distributed via shfl; ELLW=32 => no tail path
//   - gathers unrolled by 8 (MLP 8)
// out[n] = h[n]^2 + sum w*h16[col]. Resets replay state.
// ---------------------------------------------------------------------------
__global__ void k_agg(float* __restrict__ out) {
    if (blockIdx.x == 0 && threadIdx.x < D) {
        g_sum[threadIdx.x] = 0.f;
        g_sumsq[threadIdx.x] = 0.f;
    }

    int n = (int)((blockIdx.x * (unsigned)blockDim.x + threadIdx.x) >> 5);
    int lane = threadIdx.x & 31;
    if (n >= N_NODES) return;

    const int2* row = &g_ell[(size_t)n * ELLW];

    // all three independent loads issued before any dependent work
    int cnt = g_cnt[n];
    int2 my_e = row[lane];                                    // coalesced 256B
    float4 hv = *(const float4*)&g_h[(size_t)n * D + 4 * lane];  // own row

    int m = cnt < ELLW ? cnt : ELLW;
    if (lane == 0 && cnt != 0) g_cnt[n] = 0;

    float4 a0 = make_float4(0.f, 0.f, 0.f, 0.f);
    float4 a1 = make_float4(0.f, 0.f, 0.f, 0.f);
    float4 a2 = make_float4(0.f, 0.f, 0.f, 0.f);
    float4 a3 = make_float4(0.f, 0.f, 0.f, 0.f);

    int j = 0;
    for (; j + 7 < m; j += 8) {
#pragma unroll
        for (int q = 0; q < 8; q += 4) {
            int c0 = __shfl_sync(0xffffffffu, my_e.x, j + q);
            int c1 = __shfl_sync(0xffffffffu, my_e.x, j + q + 1);
            int c2 = __shfl_sync(0xffffffffu, my_e.x, j + q + 2);
            int c3 = __shfl_sync(0xffffffffu, my_e.x, j + q + 3);
            float w0 = __int_as_float(__shfl_sync(0xffffffffu, my_e.y, j + q));
            float w1 = __int_as_float(__shfl_sync(0xffffffffu, my_e.y, j + q + 1));
            float w2 = __int_as_float(__shfl_sync(0xffffffffu, my_e.y, j + q + 2));
            float w3 = __int_as_float(__shfl_sync(0xffffffffu, my_e.y, j + q + 3));
            uint2 r0 = *(const uint2*)&g_h16[(size_t)c0 * D + 4 * lane];
            uint2 r1 = *(const uint2*)&g_h16[(size_t)c1 * D + 4 * lane];
            uint2 r2 = *(const uint2*)&g_h16[(size_t)c2 * D + 4 * lane];
            uint2 r3 = *(const uint2*)&g_h16[(size_t)c3 * D + 4 * lane];
            float2 v0a = __half22float2(*(const __half2*)&r0.x);
            float2 v0b = __half22float2(*(const __half2*)&r0.y);
            float2 v1a = __half22float2(*(const __half2*)&r1.x);
            float2 v1b = __half22float2(*(const __half2*)&r1.y);
            float2 v2a = __half22float2(*(const __half2*)&r2.x);
            float2 v2b = __half22float2(*(const __half2*)&r2.y);
            float2 v3a = __half22float2(*(const __half2*)&r3.x);
            float2 v3b = __half22float2(*(const __half2*)&r3.y);
            a0.x = fmaf(w0, v0a.x, a0.x); a0.y = fmaf(w0, v0a.y, a0.y);
            a0.z = fmaf(w0, v0b.x, a0.z); a0.w = fmaf(w0, v0b.y, a0.w);
            a1.x = fmaf(w1, v1a.x, a1.x); a1.y = fmaf(w1, v1a.y, a1.y);
            a1.z = fmaf(w1, v1b.x, a1.z); a1.w = fmaf(w1, v1b.y, a1.w);
            a2.x = fmaf(w2, v2a.x, a2.x); a2.y = fmaf(w2, v2a.y, a2.y);
            a2.z = fmaf(w2, v2b.x, a2.z); a2.w = fmaf(w2, v2b.y, a2.w);
            a3.x = fmaf(w3, v3a.x, a3.x); a3.y = fmaf(w3, v3a.y, a3.y);
            a3.z = fmaf(w3, v3b.x, a3.z); a3.w = fmaf(w3, v3b.y, a3.w);
        }
    }
    for (; j + 3 < m; j += 4) {
        int c0 = __shfl_sync(0xffffffffu, my_e.x, j);
        int c1 = __shfl_sync(0xffffffffu, my_e.x, j + 1);
        int c2 = __shfl_sync(0xffffffffu, my_e.x, j + 2);
        int c3 = __shfl_sync(0xffffffffu, my_e.x, j + 3);
        float w0 = __int_as_float(__shfl_sync(0xffffffffu, my_e.y, j));
        float w1 = __int_as_float(__shfl_sync(0xffffffffu, my_e.y, j + 1));
        float w2 = __int_as_float(__shfl_sync(0xffffffffu, my_e.y, j + 2));
        float w3 = __int_as_float(__shfl_sync(0xffffffffu, my_e.y, j + 3));
        uint2 r0 = *(const uint2*)&g_h16[(size_t)c0 * D + 4 * lane];
        uint2 r1 = *(const uint2*)&g_h16[(size_t)c1 * D + 4 * lane];
        uint2 r2 = *(const uint2*)&g_h16[(size_t)c2 * D + 4 * lane];
        uint2 r3 = *(const uint2*)&g_h16[(size_t)c3 * D + 4 * lane];
        float2 v0a = __half22float2(*(const __half2*)&r0.x);
        float2 v0b = __half22float2(*(const __half2*)&r0.y);
        float2 v1a = __half22float2(*(const __half2*)&r1.x);
        float2 v1b = __half22float2(*(const __half2*)&r1.y);
        float2 v2a = __half22float2(*(const __half2*)&r2.x);
        float2 v2b = __half22float2(*(const __half2*)&r2.y);
        float2 v3a = __half22float2(*(const __half2*)&r3.x);
        float2 v3b = __half22float2(*(const __half2*)&r3.y);
        a0.x = fmaf(w0, v0a.x, a0.x); a0.y = fmaf(w0, v0a.y, a0.y);
        a0.z = fmaf(w0, v0b.x, a0.z); a0.w = fmaf(w0, v0b.y, a0.w);
        a1.x = fmaf(w1, v1a.x, a1.x); a1.y = fmaf(w1, v1a.y, a1.y);
        a1.z = fmaf(w1, v1b.x, a1.z); a1.w = fmaf(w1, v1b.y, a1.w);
        a2.x = fmaf(w2, v2a.x, a2.x); a2.y = fmaf(w2, v2a.y, a2.y);
        a2.z = fmaf(w2, v2b.x, a2.z); a2.w = fmaf(w2, v2b.y, a2.w);
        a3.x = fmaf(w3, v3a.x, a3.x); a3.y = fmaf(w3, v3a.y, a3.y);
        a3.z = fmaf(w3, v3b.x, a3.z); a3.w = fmaf(w3, v3b.y, a3.w);
    }
    for (; j < m; j++) {
        int c0 = __shfl_sync(0xffffffffu, my_e.x, j);
        float w0 = __int_as_float(__shfl_sync(0xffffffffu, my_e.y, j));
        uint2 r0 = *(const uint2*)&g_h16[(size_t)c0 * D + 4 * lane];
        float2 v0a = __half22float2(*(const __half2*)&r0.x);
        float2 v0b = __half22float2(*(const __half2*)&r0.y);
        a0.x = fmaf(w0, v0a.x, a0.x); a0.y = fmaf(w0, v0a.y, a0.y);
        a0.z = fmaf(w0, v0b.x, a0.z); a0.w = fmaf(w0, v0b.y, a0.w);
    }

    a0.x += a1.x + a2.x + a3.x;
    a0.y += a1.y + a2.y + a3.y;
    a0.z += a1.z + a2.z + a3.z;
    a0.w += a1.w + a2.w + a3.w;

    float4 o;
    o.x = fmaf(hv.x, hv.x, a0.x);
    o.y = fmaf(hv.y, hv.y, a0.y);
    o.z = fmaf(hv.z, hv.z, a0.z);
    o.w = fmaf(hv.w, hv.w, a0.w);
    *(float4*)&out[(size_t)n * D + 4 * lane] = o;
}

// ---------------------------------------------------------------------------
extern "C" void kernel_launch(void* const* d_in, const int* in_sizes, int n_in,
                              void* d_out, int out_size) {
    const float* x     = (const float*)d_in[0];
    const int*   eidx  = (const int*)d_in[1];
    const float* ew    = (const float*)d_in[2];
    const float* gamma = (const float*)d_in[3];
    const float* beta  = (const float*)d_in[4];
    const float* W     = (const float*)d_in[5];
    float* out = (float*)d_out;

    k_pre<<<PRE_BLOCKS, PRE_T>>>((const float4*)x, eidx, ew);

    const size_t smem = (size_t)D * WP2 * 8
                      + (size_t)(GEMM_WARPS * TM * D + 2 * D) * sizeof(float);
    cudaFuncSetAttribute(k_gemm, cudaFuncAttributeMaxDynamicSharedMemorySize, (int)smem);
    k_gemm<<<304, 256, smem>>>(x, W, gamma, beta);

    k_agg<<<(N_NODES * 32 + 255) / 256, 256>>>(out);
}

// round 17
// speedup vs baseline: 1.1522x; 1.1522x over previous
#include <cuda_runtime.h>
#include <cuda_fp16.h>
#include <cstdint>

#define N_NODES 100000
#define D 128
#define N_EDGES 400000
#define BN_EPS 1e-5f

#define GEMM_WARPS 8
#define TM 8            // rows per warp
#define WP2 66          // packed-W row stride in ull (64 pairs + 2 pad)

#define ELLW 32         // padded edges per node; P(deg>32)*N ~ 1e-15 for Poisson(4)

#define CS_BLOCKS 592
#define PRE_T 256
#define BUILD_BLOCKS ((N_EDGES + PRE_T - 1) / PRE_T)
#define PRE_BLOCKS (CS_BLOCKS + BUILD_BLOCKS)

// ---------------------------------------------------------------------------
// Scratch (device globals only). Zero-initialized; k_agg restores zero state.
// g_h16 is the ONLY h array (25.6 MB -> fully L2-resident for the gather).
// ---------------------------------------------------------------------------
__device__ float  g_sum[D];
__device__ float  g_sumsq[D];
__device__ __half g_h16[(size_t)N_NODES * D];   // fp16 h (gather + own-row)

__device__ int   g_cnt[N_NODES];
__device__ int2  g_ell[(size_t)N_NODES * ELLW];

// ---------------------------------------------------------------------------
// K1 "pre": fused column-stats + ELL build (two block ranges). [frozen]
// ---------------------------------------------------------------------------
__global__ void __launch_bounds__(PRE_T) k_pre(const float4* __restrict__ x4,
                                               const int* __restrict__ eidx,
                                               const float* __restrict__ ew) {
    if (blockIdx.x < CS_BLOCKS) {
        const int N4 = N_NODES * D / 4;
        int gtid = blockIdx.x * PRE_T + threadIdx.x;

        float s0 = 0.f, s1 = 0.f, s2 = 0.f, s3 = 0.f;
        float q0 = 0.f, q1 = 0.f, q2 = 0.f, q3 = 0.f;
#pragma unroll 8
        for (int i = gtid; i < N4; i += CS_BLOCKS * PRE_T) {
            float4 v = __ldg(&x4[i]);
            s0 += v.x; q0 += v.x * v.x;
            s1 += v.y; q1 += v.y * v.y;
            s2 += v.z; q2 += v.z * v.z;
            s3 += v.w; q3 += v.w * v.w;
        }

        __shared__ float ss[D];
        __shared__ float sq[D];
        int t = threadIdx.x;
        if (t < D) { ss[t] = 0.f; sq[t] = 0.f; }
        __syncthreads();

        int c0 = (gtid & 31) * 4;
        atomicAdd(&ss[c0 + 0], s0); atomicAdd(&sq[c0 + 0], q0);
        atomicAdd(&ss[c0 + 1], s1); atomicAdd(&sq[c0 + 1], q1);
        atomicAdd(&ss[c0 + 2], s2); atomicAdd(&sq[c0 + 2], q2);
        atomicAdd(&ss[c0 + 3], s3); atomicAdd(&sq[c0 + 3], q3);
        __syncthreads();

        if (t < D) {
            atomicAdd(&g_sum[t], ss[t]);
            atomicAdd(&g_sumsq[t], sq[t]);
        }
    } else {
        int e = (blockIdx.x - CS_BLOCKS) * PRE_T + threadIdx.x;
        if (e >= N_EDGES) return;
        int r = eidx[e];
        int c = eidx[N_EDGES + e];
        float w = ew[e];
        int pos = atomicAdd(&g_cnt[r], 1);
        if (pos < ELLW) {
            g_ell[(size_t)r * ELLW + pos] = make_int2(c, __float_as_int(w));
        }
    }
}

// ---------------------------------------------------------------------------
// K2: fused stats -> BN -> ReLU -> GEMM (R11 core, frozen). Epilogue writes
// ONLY the fp16 h (halves the store traffic; keeps h16 L2-resident for agg).
// ---------------------------------------------------------------------------
extern __shared__ float sm_gemm[];

__global__ void __launch_bounds__(256, 2) k_gemm(const float* __restrict__ x,
                                                 const float* __restrict__ W,
                                                 const float* __restrict__ gamma,
                                                 const float* __restrict__ beta) {
    unsigned long long* Wp = (unsigned long long*)sm_gemm;    // D * WP2 ull
    float* ysh = (float*)(Wp + D * WP2);                      // GEMM_WARPS*TM*D
    float* ssc = ysh + GEMM_WARPS * TM * D;                   // D
    float* ssh = ssc + D;                                     // D

    int tid = threadIdx.x;

    for (int i = tid; i < D * (D / 2); i += blockDim.x) {
        int jp = i / D;
        int k = i - jp * D;
        float w0 = W[(2 * jp) * D + k];
        float w1 = W[(2 * jp + 1) * D + k];
        unsigned long long pk;
        asm("mov.b64 %0, {%1,%2};" : "=l"(pk) : "f"(w0), "f"(w1));
        Wp[k * WP2 + jp] = pk;
    }
    if (tid < D) {
        const float inv_n = 1.f / (float)N_NODES;
        float mu = g_sum[tid] * inv_n;
        float var = g_sumsq[tid] * inv_n - mu * mu;
        float rs = rsqrtf(var + BN_EPS);
        float sc = gamma[tid] * rs;
        ssc[tid] = sc;
        ssh[tid] = beta[tid] - mu * sc;
    }
    __syncthreads();

    int warp = tid >> 5;
    int lane = tid & 31;
    float* myY = ysh + warp * TM * D;

    float sc[4], sh[4];
#pragma unroll
    for (int i = 0; i < 4; i++) {
        sc[i] = ssc[4 * lane + i];
        sh[i] = ssh[4 * lane + i];
    }

    const int ntiles = (N_NODES + GEMM_WARPS * TM - 1) / (GEMM_WARPS * TM);
    for (int tile = blockIdx.x; tile < ntiles; tile += gridDim.x) {
        int row0 = tile * (GEMM_WARPS * TM) + warp * TM;

        __syncwarp();
#pragma unroll
        for (int r = 0; r < TM; r++) {
            int row = row0 + r;
            if (row < N_NODES) {
                float4 v = __ldcs((const float4*)&x[(size_t)row * D + 4 * lane]);
                v.x = fmaxf(0.f, fmaf(v.x, sc[0], sh[0]));
                v.y = fmaxf(0.f, fmaf(v.y, sc[1], sh[1]));
                v.z = fmaxf(0.f, fmaf(v.z, sc[2], sh[2]));
                v.w = fmaxf(0.f, fmaf(v.w, sc[3], sh[3]));
                *(float4*)&myY[r * D + 4 * lane] = v;
            }
        }
        __syncwarp();

        unsigned long long acc[TM][2];
#pragma unroll
        for (int r = 0; r < TM; r++) { acc[r][0] = 0ULL; acc[r][1] = 0ULL; }

#pragma unroll 8
        for (int k = 0; k < D; k++) {
            unsigned long long w01, w23;
            {
                ulonglong2 wp = *(const ulonglong2*)&Wp[k * WP2 + 2 * lane];
                w01 = wp.x;
                w23 = wp.y;
            }
#pragma unroll
            for (int r = 0; r < TM; r++) {
                float yv = myY[r * D + k];
                unsigned long long yy;
                asm("mov.b64 %0, {%1,%1};" : "=l"(yy) : "f"(yv));
                asm("fma.rn.f32x2 %0, %1, %2, %0;" : "+l"(acc[r][0]) : "l"(yy), "l"(w01));
                asm("fma.rn.f32x2 %0, %1, %2, %0;" : "+l"(acc[r][1]) : "l"(yy), "l"(w23));
            }
        }

#pragma unroll
        for (int r = 0; r < TM; r++) {
            int row = row0 + r;
            if (row < N_NODES) {
                float4 hv;
                asm("mov.b64 {%0,%1}, %2;" : "=f"(hv.x), "=f"(hv.y) : "l"(acc[r][0]));
                asm("mov.b64 {%0,%1}, %2;" : "=f"(hv.z), "=f"(hv.w) : "l"(acc[r][1]));
                __half2 p0 = __floats2half2_rn(hv.x, hv.y);
                __half2 p1 = __floats2half2_rn(hv.z, hv.w);
                uint2 pk;
                pk.x = *(const unsigned int*)&p0;
                pk.y = *(const unsigned int*)&p1;
                *(uint2*)&g_h16[(size_t)row * D + 4 * lane] = pk;
            }
        }
    }
}

// ---------------------------------------------------------------------------
// K3: ELL aggregation: out[n] = h16[n]^2 (fp32 math) + sum w*h16[col].
// cnt + row[lane] + own h16 row issued up front; entries via shfl;
// out stored streaming (__stcs) and ELL read streaming (__ldcs) to keep the
// 25.6MB h16 array L2-resident for the random gather. Resets replay state.
// ---------------------------------------------------------------------------
__global__ void k_agg(float* __restrict__ out) {
    if (blockIdx.x == 0 && threadIdx.x < D) {
        g_sum[threadIdx.x] = 0.f;
        g_sumsq[threadIdx.x] = 0.f;
    }

    int n = (int)((blockIdx.x * (unsigned)blockDim.x + threadIdx.x) >> 5);
    int lane = threadIdx.x & 31;
    if (n >= N_NODES) return;

    const int2* row = &g_ell[(size_t)n * ELLW];

    // all three independent loads issued before any dependent work
    int cnt = g_cnt[n];
    int2 my_e = __ldcs(&row[lane]);                               // coalesced 256B
    uint2 own = *(const uint2*)&g_h16[(size_t)n * D + 4 * lane];  // own row (L2)

    int m = cnt < ELLW ? cnt : ELLW;
    if (lane == 0 && cnt != 0) g_cnt[n] = 0;

    float4 a0 = make_float4(0.f, 0.f, 0.f, 0.f);
    float4 a1 = make_float4(0.f, 0.f, 0.f, 0.f);
    float4 a2 = make_float4(0.f, 0.f, 0.f, 0.f);
    float4 a3 = make_float4(0.f, 0.f, 0.f, 0.f);

    int j = 0;
    for (; j + 3 < m; j += 4) {
        int c0 = __shfl_sync(0xffffffffu, my_e.x, j);
        int c1 = __shfl_sync(0xffffffffu, my_e.x, j + 1);
        int c2 = __shfl_sync(0xffffffffu, my_e.x, j + 2);
        int c3 = __shfl_sync(0xffffffffu, my_e.x, j + 3);
        float w0 = __int_as_float(__shfl_sync(0xffffffffu, my_e.y, j));
        float w1 = __int_as_float(__shfl_sync(0xffffffffu, my_e.y, j + 1));
        float w2 = __int_as_float(__shfl_sync(0xffffffffu, my_e.y, j + 2));
        float w3 = __int_as_float(__shfl_sync(0xffffffffu, my_e.y, j + 3));
        uint2 r0 = *(const uint2*)&g_h16[(size_t)c0 * D + 4 * lane];
        uint2 r1 = *(const uint2*)&g_h16[(size_t)c1 * D + 4 * lane];
        uint2 r2 = *(const uint2*)&g_h16[(size_t)c2 * D + 4 * lane];
        uint2 r3 = *(const uint2*)&g_h16[(size_t)c3 * D + 4 * lane];
        float2 v0a = __half22float2(*(const __half2*)&r0.x);
        float2 v0b = __half22float2(*(const __half2*)&r0.y);
        float2 v1a = __half22float2(*(const __half2*)&r1.x);
        float2 v1b = __half22float2(*(const __half2*)&r1.y);
        float2 v2a = __half22float2(*(const __half2*)&r2.x);
        float2 v2b = __half22float2(*(const __half2*)&r2.y);
        float2 v3a = __half22float2(*(const __half2*)&r3.x);
        float2 v3b = __half22float2(*(const __half2*)&r3.y);
        a0.x = fmaf(w0, v0a.x, a0.x); a0.y = fmaf(w0, v0a.y, a0.y);
        a0.z = fmaf(w0, v0b.x, a0.z); a0.w = fmaf(w0, v0b.y, a0.w);
        a1.x = fmaf(w1, v1a.x, a1.x); a1.y = fmaf(w1, v1a.y, a1.y);
        a1.z = fmaf(w1, v1b.x, a1.z); a1.w = fmaf(w1, v1b.y, a1.w);
        a2.x = fmaf(w2, v2a.x, a2.x); a2.y = fmaf(w2, v2a.y, a2.y);
        a2.z = fmaf(w2, v2b.x, a2.z); a2.w = fmaf(w2, v2b.y, a2.w);
        a3.x = fmaf(w3, v3a.x, a3.x); a3.y = fmaf(w3, v3a.y, a3.y);
        a3.z = fmaf(w3, v3b.x, a3.z); a3.w = fmaf(w3, v3b.y, a3.w);
    }
    for (; j < m; j++) {
        int c0 = __shfl_sync(0xffffffffu, my_e.x, j);
        float w0 = __int_as_float(__shfl_sync(0xffffffffu, my_e.y, j));
        uint2 r0 = *(const uint2*)&g_h16[(size_t)c0 * D + 4 * lane];
        float2 v0a = __half22float2(*(const __half2*)&r0.x);
        float2 v0b = __half22float2(*(const __half2*)&r0.y);
        a0.x = fmaf(w0, v0a.x, a0.x); a0.y = fmaf(w0, v0a.y, a0.y);
        a0.z = fmaf(w0, v0b.x, a0.z); a0.w = fmaf(w0, v0b.y, a0.w);
    }

    a0.x += a1.x + a2.x + a3.x;
    a0.y += a1.y + a2.y + a3.y;
    a0.z += a1.z + a2.z + a3.z;
    a0.w += a1.w + a2.w + a3.w;

    // own-row h (fp16 -> fp32), square in fp32
    float2 ha = __half22float2(*(const __half2*)&own.x);
    float2 hb = __half22float2(*(const __half2*)&own.y);
    float4 o;
    o.x = fmaf(ha.x, ha.x, a0.x);
    o.y = fmaf(ha.y, ha.y, a0.y);
    o.z = fmaf(hb.x, hb.x, a0.z);
    o.w = fmaf(hb.y, hb.y, a0.w);
    __stcs((float4*)&out[(size_t)n * D + 4 * lane], o);
}

// ---------------------------------------------------------------------------
extern "C" void kernel_launch(void* const* d_in, const int* in_sizes, int n_in,
                              void* d_out, int out_size) {
    const float* x     = (const float*)d_in[0];
    const int*   eidx  = (const int*)d_in[1];
    const float* ew    = (const float*)d_in[2];
    const float* gamma = (const float*)d_in[3];
    const float* beta  = (const float*)d_in[4];
    const float* W     = (const float*)d_in[5];
    float* out = (float*)d_out;

    k_pre<<<PRE_BLOCKS, PRE_T>>>((const float4*)x, eidx, ew);

    const size_t smem = (size_t)D * WP2 * 8
                      + (size_t)(GEMM_WARPS * TM * D + 2 * D) * sizeof(float);
    cudaFuncSetAttribute(k_gemm, cudaFuncAttributeMaxDynamicSharedMemorySize, (int)smem);
    k_gemm<<<296, 256, smem>>>(x, W, gamma, beta);   // 296 = 2 CTAs x 148 SMs

    k_agg<<<(N_NODES * 32 + 255) / 256, 256>>>(out);
}